// round 3
// baseline (speedup 1.0000x reference)
#include <cuda_runtime.h>
#include <math.h>

#define NN 64
#define CC 512
#define HWD 1024
#define KK 64
#define ALPHA 50.0f
#define EPSV 1e-12f

// scratch (no allocations allowed)
__device__ float g_Wn[CC * KK];
__device__ float g_inv[NN * HWD];
__device__ float g_sa[(size_t)NN * KK * HWD];
__device__ float g_asum[NN * KK];
__device__ float g_vlad[(size_t)NN * KK * CC];

// ---------------- kernel 1: column-normalize conv weight ----------------
__global__ __launch_bounds__(256) void kWnorm(const float* __restrict__ w) {
    __shared__ float part[4][64];
    int t = threadIdx.x;
    int k = t & 63, p = t >> 6;
    float s = 0.f;
    for (int c = p; c < CC; c += 4) { float v = w[c * KK + k]; s += v * v; }
    part[p][k] = s;
    __syncthreads();
    if (p == 0) {
        float tot = part[0][k] + part[1][k] + part[2][k] + part[3][k];
        part[0][k] = 1.f / fmaxf(sqrtf(tot), EPSV);
    }
    __syncthreads();
    float inv = part[0][k];
    for (int c = p; c < CC; c += 4) g_Wn[c * KK + k] = w[c * KK + k] * inv;
}

// ---------------- kernel 2: per-pixel inverse L2 norm over C ----------------
__global__ __launch_bounds__(256) void kXnorm(const float* __restrict__ x) {
    int idx = blockIdx.x * 256 + threadIdx.x;       // n*HW + hw
    int n = idx >> 10, hw = idx & 1023;
    const float* p = x + ((size_t)n * CC) * HWD + hw;
    float s = 0.f;
#pragma unroll 8
    for (int c = 0; c < CC; c++) { float v = p[(size_t)c * HWD]; s += v * v; }
    g_inv[idx] = 1.f / fmaxf(sqrtf(s), EPSV);
}

// ---------------- kernel 3: scale + transpose -> feature [N,HW,C] ----------------
__global__ __launch_bounds__(256) void kFeat(const float* __restrict__ x, float* __restrict__ feat) {
    __shared__ float tile[32][33];
    int n = blockIdx.z, cb = blockIdx.y * 32, hb = blockIdx.x * 32;
    int tx = threadIdx.x & 31, ty = threadIdx.x >> 5;     // 32 x 8
    float inv = g_inv[n * HWD + hb + tx];
    const float* xp = x + ((size_t)n * CC + cb) * HWD + hb;
#pragma unroll
    for (int r = 0; r < 4; r++) {
        int c = ty + r * 8;
        tile[c][tx] = xp[(size_t)c * HWD + tx] * inv;
    }
    __syncthreads();
    float* fp = feat + ((size_t)n * HWD + hb) * CC + cb;
#pragma unroll
    for (int r = 0; r < 4; r++) {
        int h = ty + r * 8;
        fp[(size_t)h * CC + tx] = tile[tx][h];
    }
}

// ---------------- kernel 4: logits GEMM + softmax ----------------
// block: one n, 128 h rows, all 64 k. sa_raw = raw logits out, g_sa = softmax.
__global__ __launch_bounds__(256) void kLogits(const float* __restrict__ feat,
                                               const float* __restrict__ bias,
                                               float* __restrict__ sa_raw) {
    __shared__ float smem[64 * 129];   // 33 KB, reused
    __shared__ float sbias[64];
    float* Fs = smem;                  // [32][129] (c-major, padded)
    float* Ws = smem + 32 * 129;       // [32][64]
    int n = blockIdx.y, hb = blockIdx.x * 128;
    int t = threadIdx.x;
    int kg = t & 7, hg = t >> 3;       // k = kg + 8j (j<8), h = hg*4 + i (i<4)
    if (t < 64) sbias[t] = bias[t];

    float acc[4][8];
#pragma unroll
    for (int i = 0; i < 4; i++)
#pragma unroll
        for (int j = 0; j < 8; j++) acc[i][j] = 0.f;

    const float* fbase = feat + ((size_t)n * HWD + hb) * CC;
    for (int cb = 0; cb < CC; cb += 32) {
        __syncthreads();
        {
            int c = t & 31, h0 = t >> 5;
#pragma unroll
            for (int r = 0; r < 16; r++) {
                int h = h0 + r * 8;
                Fs[c * 129 + h] = fbase[(size_t)h * CC + cb + c];
            }
        }
        {
            int k = t & 63, c0 = t >> 6;
#pragma unroll
            for (int r = 0; r < 8; r++) {
                int c = c0 + r * 4;
                Ws[c * 64 + k] = g_Wn[(cb + c) * KK + k];
            }
        }
        __syncthreads();
#pragma unroll 8
        for (int c = 0; c < 32; c++) {
            float f[4], w[8];
#pragma unroll
            for (int i = 0; i < 4; i++) f[i] = Fs[c * 129 + hg * 4 + i];
#pragma unroll
            for (int j = 0; j < 8; j++) w[j] = Ws[c * 64 + kg + j * 8];
#pragma unroll
            for (int i = 0; i < 4; i++)
#pragma unroll
                for (int j = 0; j < 8; j++) acc[i][j] += f[i] * w[j];
        }
    }
    __syncthreads();
    // stash logits tile in smem [64][129]
    float* Ls = smem;
#pragma unroll
    for (int i = 0; i < 4; i++)
#pragma unroll
        for (int j = 0; j < 8; j++)
            Ls[(kg + j * 8) * 129 + hg * 4 + i] = acc[i][j];
    __syncthreads();
    // write raw logits (coalesced along h)
    {
        float* sp = sa_raw + ((size_t)n * KK) * HWD + hb;
        int h = t & 127, khalf = t >> 7;
#pragma unroll
        for (int r = 0; r < 32; r++) {
            int k = r * 2 + khalf;
            sp[(size_t)k * HWD + h] = Ls[k * 129 + h];
        }
    }
    __syncthreads();
    // softmax over k per h (threads 0..127)
    if (t < 128) {
        int h = t;
        float m = -1e30f;
#pragma unroll
        for (int k = 0; k < 64; k++)
            m = fmaxf(m, (Ls[k * 129 + h] + sbias[k]) * ALPHA);
        float sum = 0.f;
#pragma unroll
        for (int k = 0; k < 64; k++) {
            float e = __expf((Ls[k * 129 + h] + sbias[k]) * ALPHA - m);
            sum += e;
            Ls[k * 129 + h] = e;
        }
        float r = 1.f / sum;
        float* sap = g_sa + ((size_t)n * KK) * HWD + hb + h;
#pragma unroll
        for (int k = 0; k < 64; k++)
            sap[(size_t)k * HWD] = Ls[k * 129 + h] * r;
    }
}

// ---------------- block reduce helper ----------------
__device__ __forceinline__ float blockReduce128(float v, float* red) {
#pragma unroll
    for (int o = 16; o > 0; o >>= 1) v += __shfl_xor_sync(0xffffffffu, v, o);
    int w = threadIdx.x >> 5;
    if ((threadIdx.x & 31) == 0) red[w] = v;
    __syncthreads();
    float tot = red[0] + red[1] + red[2] + red[3];
    return tot;
}

// ---------------- kernel 5: asum[n,k] = sum_h soft_assign ----------------
__global__ __launch_bounds__(128) void kAsum() {
    __shared__ float red[4];
    int row = blockIdx.x;   // n*K + k
    const float* p = g_sa + (size_t)row * HWD;
    float s = 0.f;
    for (int h = threadIdx.x; h < HWD; h += 128) s += p[h];
    float tot = blockReduce128(s, red);
    if (threadIdx.x == 0) g_asum[row] = tot;
}

// ---------------- kernel 6: vlad GEMM ----------------
// block: one n, C-tile of 128, all 64 k. vlad[k][c] = sum_h a[k][h]*f[h][c] - asum[k]*w[c][k]
__global__ __launch_bounds__(256) void kVlad(const float* __restrict__ feat,
                                             const float* __restrict__ w) {
    __shared__ float As[64 * 33];    // [k][h]
    __shared__ float Fs[32 * 128];   // [h][c]
    int n = blockIdx.y, cb = blockIdx.x * 128;
    int t = threadIdx.x;
    int cg = t & 31, kg = t >> 5;    // c = cg + 32j (j<4), k = kg + 8i (i<8)
    float acc[8][4];
#pragma unroll
    for (int i = 0; i < 8; i++)
#pragma unroll
        for (int j = 0; j < 4; j++) acc[i][j] = 0.f;

    const float* abase = g_sa + ((size_t)n * KK) * HWD;
    const float* fbase = feat + (size_t)n * HWD * CC + cb;
    for (int hb = 0; hb < HWD; hb += 32) {
        __syncthreads();
        {
            int h = t & 31, k0 = t >> 5;
#pragma unroll
            for (int r = 0; r < 8; r++) {
                int k = k0 + r * 8;
                As[k * 33 + h] = abase[(size_t)k * HWD + hb + h];
            }
        }
        {
            int c = t & 127, h0 = t >> 7;
#pragma unroll
            for (int r = 0; r < 16; r++) {
                int h = h0 + r * 2;
                Fs[h * 128 + c] = fbase[(size_t)(hb + h) * CC + c];
            }
        }
        __syncthreads();
#pragma unroll 8
        for (int h = 0; h < 32; h++) {
            float a[8], f[4];
#pragma unroll
            for (int i = 0; i < 8; i++) a[i] = As[(kg + i * 8) * 33 + h];
#pragma unroll
            for (int j = 0; j < 4; j++) f[j] = Fs[h * 128 + cg + j * 32];
#pragma unroll
            for (int i = 0; i < 8; i++)
#pragma unroll
                for (int j = 0; j < 4; j++) acc[i][j] += a[i] * f[j];
        }
    }
#pragma unroll
    for (int i = 0; i < 8; i++) {
        int k = kg + i * 8;
        float as = g_asum[n * KK + k];
#pragma unroll
        for (int j = 0; j < 4; j++) {
            int c = cb + cg + j * 32;
            g_vlad[((size_t)n * KK + k) * CC + c] = acc[i][j] - as * w[c * KK + k];
        }
    }
}

// ---------------- kernel 7: intra-normalize vlad rows -> output ----------------
__global__ __launch_bounds__(128) void kVnorm(float* __restrict__ out) {
    __shared__ float red[4];
    __shared__ float sinv;
    int row = blockIdx.x;   // n*K + k
    const float* p = g_vlad + (size_t)row * CC;
    int t = threadIdx.x;
    float v[4];
    float s = 0.f;
#pragma unroll
    for (int j = 0; j < 4; j++) { v[j] = p[t + j * 128]; s += v[j] * v[j]; }
    float tot = blockReduce128(s, red);
    if (t == 0) sinv = 1.f / fmaxf(sqrtf(tot), EPSV);
    __syncthreads();
    float inv = sinv;
    float* o = out + (size_t)row * CC;
#pragma unroll
    for (int j = 0; j < 4; j++) o[t + j * 128] = v[j] * inv;
}

extern "C" void kernel_launch(void* const* d_in, const int* in_sizes, int n_in,
                              void* d_out, int out_size) {
    const float* x = (const float*)d_in[0];     // [N,C,H,W]
    const float* w = (const float*)d_in[1];     // [C,K]
    const float* b = (const float*)d_in[2];     // [K]
    float* out = (float*)d_out;

    const size_t VLAD_OFF = 0;
    const size_t SA_OFF = (size_t)NN * KK * CC;                    // 2097152
    const size_t FEAT_OFF = SA_OFF + (size_t)NN * KK * HWD;        // 6291456

    kWnorm<<<1, 256>>>(w);
    kXnorm<<<(NN * HWD) / 256, 256>>>(x);
    kFeat<<<dim3(HWD / 32, CC / 32, NN), 256>>>(x, out + FEAT_OFF);
    kLogits<<<dim3(HWD / 128, NN), 256>>>(out + FEAT_OFF, b, out + SA_OFF);
    kAsum<<<NN * KK, 128>>>();
    kVlad<<<dim3(CC / 128, NN), 256>>>(out + FEAT_OFF, w);
    kVnorm<<<NN * KK, 128>>>(out + VLAD_OFF);
}

// round 6
// speedup vs baseline: 1.0577x; 1.0577x over previous
#include <cuda_runtime.h>
#include <math.h>

#define NN 64
#define CC 512
#define HWD 1024
#define KK 64
#define ALPHA 50.0f
#define EPSV 1e-12f

typedef unsigned long long ull;

// scratch (no allocations allowed)
__device__ float g_Wn[CC * KK];
__device__ float g_sa[(size_t)NN * KK * HWD];
__device__ float g_asum[NN * KK];
__device__ float g_vlad[(size_t)NN * KK * CC];

__device__ __forceinline__ void ffma2(ull& d, ull a, ull b) {
    asm("fma.rn.f32x2 %0, %1, %2, %0;" : "+l"(d) : "l"(a), "l"(b));
}
__device__ __forceinline__ float2 ull2f2(ull v) {
    float2 r;
    r.x = __uint_as_float((unsigned)(v & 0xffffffffu));
    r.y = __uint_as_float((unsigned)(v >> 32));
    return r;
}

// ---------------- kernel 1: column-normalize conv weight ----------------
__global__ __launch_bounds__(256) void kWnorm(const float* __restrict__ w) {
    __shared__ float part[4][64];
    int t = threadIdx.x;
    int k = t & 63, p = t >> 6;
    float s = 0.f;
    for (int c = p; c < CC; c += 4) { float v = w[c * KK + k]; s += v * v; }
    part[p][k] = s;
    __syncthreads();
    if (p == 0) {
        float tot = part[0][k] + part[1][k] + part[2][k] + part[3][k];
        part[0][k] = 1.f / fmaxf(sqrtf(tot), EPSV);
    }
    __syncthreads();
    float inv = part[0][k];
    for (int c = p; c < CC; c += 4) g_Wn[c * KK + k] = w[c * KK + k] * inv;
}

// ---------------- kernel 2: fused L2-normalize + transpose -> feature [N,HW,C] ----------------
// block: one n, 16 hw pixels, all 512 c. Reads x once, writes feat once.
__global__ __launch_bounds__(256) void kNormFeat(const float* __restrict__ x,
                                                 float* __restrict__ feat) {
    __shared__ float tile[CC * 17];    // [c][hw] pad 17
    __shared__ float red[256];
    __shared__ float sinv[16];
    int n = blockIdx.y, p0 = blockIdx.x * 16;
    int t = threadIdx.x;
    int hw = t & 15, c0 = t >> 4;      // c0: 0..15

    const float* xp = x + ((size_t)n * CC) * HWD + p0 + hw;
    float s = 0.f;
#pragma unroll
    for (int r = 0; r < 32; r++) {
        int c = c0 + r * 16;
        float v = xp[(size_t)c * HWD];
        tile[c * 17 + hw] = v;
        s += v * v;
    }
    red[c0 * 16 + hw] = s;
    __syncthreads();
    if (t < 16) {
        float tot = 0.f;
#pragma unroll
        for (int cp = 0; cp < 16; cp++) tot += red[cp * 16 + t];
        sinv[t] = 1.f / fmaxf(sqrtf(tot), EPSV);
    }
    __syncthreads();
    float* fb = feat + ((size_t)n * HWD + p0) * CC;
#pragma unroll
    for (int r = 0; r < 32; r++) {
        int idx = r * 256 + t;
        int h = idx >> 9, c = idx & 511;
        fb[(size_t)h * CC + c] = tile[c * 17 + h] * sinv[h];
    }
}

// ---------------- kernel 3: logits GEMM (f32x2) + softmax ----------------
// block: one n, 128 h rows, all 64 k.
// thread: kg=t&7 -> k pairs {kg*2+j*16, +1}, hg=t>>3 -> h = hg*4+i
__global__ __launch_bounds__(256) void kLogits(const float* __restrict__ feat,
                                               const float* __restrict__ bias,
                                               float* __restrict__ sa_raw) {
    __shared__ float smem[32 * 129 * 2 + 32 * 64];   // Fdup (float2[32][129]) + Ws[32][64]
    __shared__ float sbias[64];
    float2* Fd2 = (float2*)smem;
    float* Ws = smem + 32 * 129 * 2;
    int n = blockIdx.y, hb = blockIdx.x * 128;
    int t = threadIdx.x;
    int kg = t & 7, hg = t >> 3;
    if (t < 64) sbias[t] = bias[t];

    ull acc[4][4];
#pragma unroll
    for (int i = 0; i < 4; i++)
#pragma unroll
        for (int j = 0; j < 4; j++) acc[i][j] = 0ull;

    const float* fbase = feat + ((size_t)n * HWD + hb) * CC;
    for (int cb = 0; cb < CC; cb += 32) {
        __syncthreads();
        {
            int c = t & 31, h0 = t >> 5;
#pragma unroll
            for (int r = 0; r < 16; r++) {
                int h = h0 + r * 8;
                float v = fbase[(size_t)h * CC + cb + c];
                Fd2[c * 129 + h] = make_float2(v, v);
            }
        }
        {
            int k = t & 63, c0 = t >> 6;
#pragma unroll
            for (int r = 0; r < 8; r++) {
                int c = c0 + r * 4;
                Ws[c * 64 + k] = g_Wn[(cb + c) * KK + k];
            }
        }
        __syncthreads();
#pragma unroll 8
        for (int c = 0; c < 32; c++) {
            ull fd[4], wp[4];
            const ull* fr = (const ull*)(Fd2 + c * 129 + hg * 4);
#pragma unroll
            for (int i = 0; i < 4; i++) fd[i] = fr[i];
            const ull* wr = (const ull*)(Ws + c * 64 + kg * 2);
#pragma unroll
            for (int j = 0; j < 4; j++) wp[j] = wr[j * 8];
#pragma unroll
            for (int i = 0; i < 4; i++)
#pragma unroll
                for (int j = 0; j < 4; j++) ffma2(acc[i][j], fd[i], wp[j]);
        }
    }
    __syncthreads();
    // stash logits tile in smem Ls[64][129]
    float* Ls = smem;
#pragma unroll
    for (int i = 0; i < 4; i++)
#pragma unroll
        for (int j = 0; j < 4; j++) {
            float2 v = ull2f2(acc[i][j]);
            int k = kg * 2 + j * 16, h = hg * 4 + i;
            Ls[k * 129 + h] = v.x;
            Ls[(k + 1) * 129 + h] = v.y;
        }
    __syncthreads();
    // write raw logits (coalesced along h)
    {
        float* sp = sa_raw + ((size_t)n * KK) * HWD + hb;
        int h = t & 127, khalf = t >> 7;
#pragma unroll
        for (int r = 0; r < 32; r++) {
            int k = r * 2 + khalf;
            sp[(size_t)k * HWD + h] = Ls[k * 129 + h];
        }
    }
    __syncthreads();
    // softmax over k per h (threads 0..127)
    if (t < 128) {
        int h = t;
        float m = -1e30f;
#pragma unroll
        for (int k = 0; k < 64; k++)
            m = fmaxf(m, (Ls[k * 129 + h] + sbias[k]) * ALPHA);
        float sum = 0.f;
#pragma unroll
        for (int k = 0; k < 64; k++) {
            float e = __expf((Ls[k * 129 + h] + sbias[k]) * ALPHA - m);
            sum += e;
            Ls[k * 129 + h] = e;
        }
        float r = 1.f / sum;
        float* sap = g_sa + ((size_t)n * KK) * HWD + hb + h;
#pragma unroll
        for (int k = 0; k < 64; k++)
            sap[(size_t)k * HWD] = Ls[k * 129 + h] * r;
    }
}

// ---------------- block reduce helper ----------------
__device__ __forceinline__ float blockReduce128(float v, float* red) {
#pragma unroll
    for (int o = 16; o > 0; o >>= 1) v += __shfl_xor_sync(0xffffffffu, v, o);
    int w = threadIdx.x >> 5;
    if ((threadIdx.x & 31) == 0) red[w] = v;
    __syncthreads();
    return red[0] + red[1] + red[2] + red[3];
}

// ---------------- kernel 4: asum[n,k] = sum_h soft_assign ----------------
__global__ __launch_bounds__(128) void kAsum() {
    __shared__ float red[4];
    int row = blockIdx.x;
    const float* p = g_sa + (size_t)row * HWD;
    float s = 0.f;
    for (int h = threadIdx.x; h < HWD; h += 128) s += p[h];
    float tot = blockReduce128(s, red);
    if (threadIdx.x == 0) g_asum[row] = tot;
}

// ---------------- kernel 5: vlad GEMM (f32x2) ----------------
// block: one n, 128-c tile, all 64 k.
// thread: cg=t&31 -> c pairs {(cg+j*32)*2, +1}, kg=t>>5 -> k = kg+i*8
__global__ __launch_bounds__(256) void kVlad(const float* __restrict__ feat,
                                             const float* __restrict__ w) {
    __shared__ float2 Ad2[64 * 33];  // [k][h] duplicated pairs, pad 33
    __shared__ float Fs[32 * 128];   // [h][c]
    int n = blockIdx.y, cb = blockIdx.x * 128;
    int t = threadIdx.x;
    int cg = t & 31, kg = t >> 5;
    ull acc[8][2];
#pragma unroll
    for (int i = 0; i < 8; i++) { acc[i][0] = 0ull; acc[i][1] = 0ull; }

    const float* abase = g_sa + ((size_t)n * KK) * HWD;
    const float* fbase = feat + (size_t)n * HWD * CC + cb;
    for (int hb = 0; hb < HWD; hb += 32) {
        __syncthreads();
        {
            int h = t & 31, k0 = t >> 5;
#pragma unroll
            for (int r = 0; r < 8; r++) {
                int k = k0 + r * 8;
                float v = abase[(size_t)k * HWD + hb + h];
                Ad2[k * 33 + h] = make_float2(v, v);
            }
        }
        {
            int c = t & 127, h0 = t >> 7;
#pragma unroll
            for (int r = 0; r < 16; r++) {
                int h = h0 + r * 2;
                Fs[h * 128 + c] = fbase[(size_t)(hb + h) * CC + c];
            }
        }
        __syncthreads();
#pragma unroll 4
        for (int h = 0; h < 32; h++) {
            ull ad[8], fp[2];
            const ull* ar = (const ull*)Ad2;
#pragma unroll
            for (int i = 0; i < 8; i++) ad[i] = ar[(kg + i * 8) * 33 + h];
            const ull* fr = (const ull*)(Fs + h * 128);
#pragma unroll
            for (int j = 0; j < 2; j++) fp[j] = fr[cg + j * 32];
#pragma unroll
            for (int i = 0; i < 8; i++)
#pragma unroll
                for (int j = 0; j < 2; j++) ffma2(acc[i][j], ad[i], fp[j]);
        }
    }
#pragma unroll
    for (int i = 0; i < 8; i++) {
        int k = kg + i * 8;
        float as = g_asum[n * KK + k];
        float2* vout = (float2*)(g_vlad + ((size_t)n * KK + k) * CC + cb);
#pragma unroll
        for (int j = 0; j < 2; j++) {
            int p = cg + j * 32;
            int c = cb + 2 * p;
            float2 v = ull2f2(acc[i][j]);
            v.x -= as * w[c * KK + k];
            v.y -= as * w[(c + 1) * KK + k];
            vout[p] = v;
        }
    }
}

// ---------------- kernel 6: intra-normalize vlad rows -> output ----------------
__global__ __launch_bounds__(128) void kVnorm(float* __restrict__ out) {
    __shared__ float red[4];
    __shared__ float sinv;
    int row = blockIdx.x;
    const float* p = g_vlad + (size_t)row * CC;
    int t = threadIdx.x;
    float v[4];
    float s = 0.f;
#pragma unroll
    for (int j = 0; j < 4; j++) { v[j] = p[t + j * 128]; s += v[j] * v[j]; }
    float tot = blockReduce128(s, red);
    if (t == 0) sinv = 1.f / fmaxf(sqrtf(tot), EPSV);
    __syncthreads();
    float inv = sinv;
    float* o = out + (size_t)row * CC;
#pragma unroll
    for (int j = 0; j < 4; j++) o[t + j * 128] = v[j] * inv;
}

extern "C" void kernel_launch(void* const* d_in, const int* in_sizes, int n_in,
                              void* d_out, int out_size) {
    const float* x = (const float*)d_in[0];     // [N,C,H,W]
    const float* w = (const float*)d_in[1];     // [C,K]
    const float* b = (const float*)d_in[2];     // [K]
    float* out = (float*)d_out;

    const size_t VLAD_OFF = 0;
    const size_t SA_OFF = (size_t)NN * KK * CC;                    // 2097152
    const size_t FEAT_OFF = SA_OFF + (size_t)NN * KK * HWD;        // 6291456

    kWnorm<<<1, 256>>>(w);
    kNormFeat<<<dim3(HWD / 16, NN), 256>>>(x, out + FEAT_OFF);
    kLogits<<<dim3(HWD / 128, NN), 256>>>(out + FEAT_OFF, b, out + SA_OFF);
    kAsum<<<NN * KK, 128>>>();
    kVlad<<<dim3(CC / 128, NN), 256>>>(out + FEAT_OFF, w);
    kVnorm<<<NN * KK, 128>>>(out + VLAD_OFF);
}

// round 8
// speedup vs baseline: 1.3409x; 1.2678x over previous
#include <cuda_runtime.h>
#include <cuda_bf16.h>
#include <math.h>
#include <stdint.h>

#define NN 64
#define CC 512
#define HWD 1024
#define KK 64
#define ALPHA 50.0f
#define EPSV 1e-12f

// ---- device scratch (no allocs allowed) ----
__device__ __nv_bfloat16 g_WnT_hi[KK * CC], g_WnT_lo[KK * CC];   // [k][c]
__device__ float g_inv[NN * HWD];
__device__ __nv_bfloat16 g_saT_hi[(size_t)NN * KK * HWD];        // [n][k][h]
__device__ __nv_bfloat16 g_saT_lo[(size_t)NN * KK * HWD];
__device__ float g_psum[NN * KK * 8];
__device__ float g_asum[NN * KK];
__device__ float g_vlad[(size_t)NN * KK * CC];

// ---- smem layout (bytes). A tiles 128 rows x 72 bf16 (144B pitch); B 64 rows. ----
#define SM_AHI 0
#define SM_ALO 18432
#define SM_BHI 36864
#define SM_BLO 46080
#define SM_AUX 55296
#define SMEM_BYTES 55808
#define PITCHB 144

__device__ __forceinline__ uint32_t smem_u32(const void* p) {
    uint32_t a;
    asm("{ .reg .u64 t; cvta.to.shared.u64 t, %1; cvt.u32.u64 %0, t; }" : "=r"(a) : "l"(p));
    return a;
}
__device__ __forceinline__ void ldm4(uint32_t* r, uint32_t addr) {
    asm volatile("ldmatrix.sync.aligned.m8n8.x4.shared.b16 {%0,%1,%2,%3}, [%4];"
                 : "=r"(r[0]), "=r"(r[1]), "=r"(r[2]), "=r"(r[3]) : "r"(addr));
}
__device__ __forceinline__ void mma16816(float* d, const uint32_t* a, const uint32_t* b) {
    asm volatile(
        "mma.sync.aligned.m16n8k16.row.col.f32.bf16.bf16.f32 "
        "{%0,%1,%2,%3}, {%4,%5,%6,%7}, {%8,%9}, {%0,%1,%2,%3};"
        : "+f"(d[0]), "+f"(d[1]), "+f"(d[2]), "+f"(d[3])
        : "r"(a[0]), "r"(a[1]), "r"(a[2]), "r"(a[3]), "r"(b[0]), "r"(b[1]));
}

union B8 { uint4 u; __nv_bfloat162 b[4]; };

__device__ __forceinline__ void split8(float4 v0, float4 v1, B8& H, B8& L) {
    H.b[0] = __floats2bfloat162_rn(v0.x, v0.y);
    H.b[1] = __floats2bfloat162_rn(v0.z, v0.w);
    H.b[2] = __floats2bfloat162_rn(v1.x, v1.y);
    H.b[3] = __floats2bfloat162_rn(v1.z, v1.w);
    L.b[0] = __floats2bfloat162_rn(v0.x - __low2float(H.b[0]), v0.y - __high2float(H.b[0]));
    L.b[1] = __floats2bfloat162_rn(v0.z - __low2float(H.b[1]), v0.w - __high2float(H.b[1]));
    L.b[2] = __floats2bfloat162_rn(v1.x - __low2float(H.b[2]), v1.y - __high2float(H.b[2]));
    L.b[3] = __floats2bfloat162_rn(v1.z - __low2float(H.b[3]), v1.w - __high2float(H.b[3]));
}

// ---------------- kernel 1: normalize W columns -> bf16 hi/lo W^T ----------------
__global__ __launch_bounds__(256) void kWnorm(const float* __restrict__ w) {
    __shared__ float part[4][64];
    int t = threadIdx.x;
    int k = t & 63, p = t >> 6;
    float s = 0.f;
    for (int c = p; c < CC; c += 4) { float v = w[c * KK + k]; s += v * v; }
    part[p][k] = s;
    __syncthreads();
    if (p == 0) {
        float tot = part[0][k] + part[1][k] + part[2][k] + part[3][k];
        part[0][k] = 1.f / fmaxf(sqrtf(tot), EPSV);
    }
    __syncthreads();
    float inv = part[0][k];
    for (int c = p; c < CC; c += 4) {
        float v = w[c * KK + k] * inv;
        __nv_bfloat16 hh = __float2bfloat16(v);
        __nv_bfloat16 ll = __float2bfloat16(v - __bfloat162float(hh));
        g_WnT_hi[k * CC + c] = hh;
        g_WnT_lo[k * CC + c] = ll;
    }
}

// ---------------- kernel 2: fused L2-normalize + transpose -> feature, + g_inv ----------------
__global__ __launch_bounds__(256) void kNormFeat(const float* __restrict__ x,
                                                 float* __restrict__ feat) {
    __shared__ float tile[CC * 17];
    __shared__ float red[256];
    __shared__ float sinv[16];
    int n = blockIdx.y, p0 = blockIdx.x * 16;
    int t = threadIdx.x;
    int hw = t & 15, c0 = t >> 4;

    const float* xp = x + ((size_t)n * CC) * HWD + p0 + hw;
    float s = 0.f;
#pragma unroll
    for (int r = 0; r < 32; r++) {
        int c = c0 + r * 16;
        float v = xp[(size_t)c * HWD];
        tile[c * 17 + hw] = v;
        s += v * v;
    }
    red[c0 * 16 + hw] = s;
    __syncthreads();
    if (t < 16) {
        float tot = 0.f;
#pragma unroll
        for (int cp = 0; cp < 16; cp++) tot += red[cp * 16 + t];
        float iv = 1.f / fmaxf(sqrtf(tot), EPSV);
        sinv[t] = iv;
        g_inv[n * HWD + p0 + t] = iv;
    }
    __syncthreads();
    float* fb = feat + ((size_t)n * HWD + p0) * CC;
#pragma unroll
    for (int r = 0; r < 32; r++) {
        int idx = r * 256 + t;
        int h = idx >> 9, c = idx & 511;
        fb[(size_t)h * CC + c] = tile[c * 17 + h] * sinv[h];
    }
}

// ---------------- kernel 3: logits GEMM via mma.sync (split bf16) + softmax ----------------
// CTA: 256 thr (8 warps), one n, 128 h rows, 64 k. warp tile 32h x 32k.
__global__ __launch_bounds__(256, 2) void kLogitsMMA(const float* __restrict__ feat,
                                                     const float* __restrict__ bias,
                                                     float* __restrict__ sa_raw) {
    extern __shared__ char sm[];
    uint32_t sb = smem_u32(sm);
    int t = threadIdx.x, wid = t >> 5, l = t & 31;
    int n = blockIdx.y, hb = blockIdx.x * 128;
    float* sbias = (float*)(sm + SM_AUX);
    if (t < 64) sbias[t] = bias[t];

    int mh = (wid & 3) * 32, nk = (wid >> 2) * 32;
    // ldmatrix lane address components
    int arow = (l & 7) + ((l >> 3) & 1) * 8, acol = (l >> 4) * 8;
    int brow = (l & 7) + ((l >> 4) & 1) * 8, bcol = ((l >> 3) & 1) * 8;
    uint32_t aHiA = sb + SM_AHI + (mh + arow) * PITCHB + acol * 2;
    uint32_t aLoA = sb + SM_ALO + (mh + arow) * PITCHB + acol * 2;
    uint32_t bHiA = sb + SM_BHI + (nk + brow) * PITCHB + bcol * 2;
    uint32_t bLoA = sb + SM_BLO + (nk + brow) * PITCHB + bcol * 2;

    float acc[2][4][4];
#pragma unroll
    for (int i = 0; i < 2; i++)
#pragma unroll
        for (int j = 0; j < 4; j++)
#pragma unroll
            for (int q = 0; q < 4; q++) acc[i][j][q] = 0.f;

    const float* fb = feat + ((size_t)(n * HWD + hb)) * CC;
    int srow = t >> 1, scs = (t & 1) * 32;        // A staging: 128 rows x 2
    int sbr = t >> 2, sbs = (t & 3) * 16;         // B staging: 64 rows x 4

    for (int cb = 0; cb < CC; cb += 64) {
        __syncthreads();
        {   // stage A: feat fp32 -> hi/lo bf16
            const float4* src = (const float4*)(fb + (size_t)srow * CC + cb + scs);
#pragma unroll
            for (int q = 0; q < 4; q++) {
                B8 H, L;
                split8(src[2 * q], src[2 * q + 1], H, L);
                uint32_t off = srow * PITCHB + scs * 2 + q * 16;
                *(uint4*)(sm + SM_AHI + off) = H.u;
                *(uint4*)(sm + SM_ALO + off) = L.u;
            }
        }
        {   // stage B: WnT hi/lo bf16 passthrough
            const uint4* sh = (const uint4*)(g_WnT_hi + sbr * CC + cb + sbs);
            const uint4* sl = (const uint4*)(g_WnT_lo + sbr * CC + cb + sbs);
            uint4 h0 = sh[0], h1 = sh[1], l0 = sl[0], l1 = sl[1];
            uint32_t off = sbr * PITCHB + sbs * 2;
            *(uint4*)(sm + SM_BHI + off) = h0;
            *(uint4*)(sm + SM_BHI + off + 16) = h1;
            *(uint4*)(sm + SM_BLO + off) = l0;
            *(uint4*)(sm + SM_BLO + off + 16) = l1;
        }
        __syncthreads();
#pragma unroll
        for (int kb = 0; kb < 4; kb++) {
            uint32_t ah[2][4], al[2][4];
#pragma unroll
            for (int m2 = 0; m2 < 2; m2++) {
                ldm4(ah[m2], aHiA + m2 * 16 * PITCHB + kb * 32);
                ldm4(al[m2], aLoA + m2 * 16 * PITCHB + kb * 32);
            }
#pragma unroll
            for (int np = 0; np < 2; np++) {
                uint32_t bh[4], bl[4];
                ldm4(bh, bHiA + np * 16 * PITCHB + kb * 32);
                ldm4(bl, bLoA + np * 16 * PITCHB + kb * 32);
#pragma unroll
                for (int m2 = 0; m2 < 2; m2++)
#pragma unroll
                    for (int hf = 0; hf < 2; hf++) {
                        float* d = acc[m2][np * 2 + hf];
                        mma16816(d, ah[m2], bh + hf * 2);
                        mma16816(d, ah[m2], bl + hf * 2);
                        mma16816(d, al[m2], bh + hf * 2);
                    }
            }
        }
    }
    __syncthreads();
    // store acc -> Ls[64k][129] (reuse A region)
    float* Ls = (float*)sm;
    int rr = l >> 2, c2 = (l & 3) * 2;
#pragma unroll
    for (int m2 = 0; m2 < 2; m2++)
#pragma unroll
        for (int nb = 0; nb < 4; nb++) {
            float* d = acc[m2][nb];
            int h0 = mh + m2 * 16 + rr, k0 = nk + nb * 8 + c2;
            Ls[k0 * 129 + h0] = d[0];
            Ls[(k0 + 1) * 129 + h0] = d[1];
            Ls[k0 * 129 + h0 + 8] = d[2];
            Ls[(k0 + 1) * 129 + h0 + 8] = d[3];
        }
    __syncthreads();
    {   // raw logits out, coalesced along h
        float* sp = sa_raw + ((size_t)n * KK) * HWD + hb;
        int h2 = t & 127, kh = t >> 7;
#pragma unroll
        for (int r = 0; r < 32; r++) {
            int k = r * 2 + kh;
            sp[(size_t)k * HWD + h2] = Ls[k * 129 + h2];
        }
    }
    __syncthreads();
    if (t < 128) {   // softmax over k for h=t
        float m = -1e30f;
#pragma unroll
        for (int k = 0; k < 64; k++)
            m = fmaxf(m, (Ls[k * 129 + t] + sbias[k]) * ALPHA);
        float s = 0.f;
#pragma unroll
        for (int k = 0; k < 64; k++) {
            float e = __expf((Ls[k * 129 + t] + sbias[k]) * ALPHA - m);
            s += e;
            Ls[k * 129 + t] = e;
        }
        float r = 1.f / s;
#pragma unroll
        for (int k = 0; k < 64; k++) Ls[k * 129 + t] *= r;
    }
    __syncthreads();
    {   // soft-assign bf16 hi/lo
        int h2 = t & 127, kh = t >> 7;
        __nv_bfloat16* gh = g_saT_hi + ((size_t)n * KK) * HWD + hb;
        __nv_bfloat16* gl = g_saT_lo + ((size_t)n * KK) * HWD + hb;
#pragma unroll
        for (int r = 0; r < 32; r++) {
            int k = r * 2 + kh;
            float v = Ls[k * 129 + h2];
            __nv_bfloat16 hh = __float2bfloat16(v);
            __nv_bfloat16 ll = __float2bfloat16(v - __bfloat162float(hh));
            gh[(size_t)k * HWD + h2] = hh;
            gl[(size_t)k * HWD + h2] = ll;
        }
    }
    if (t < 64) {   // deterministic partial sums
        float s = 0.f;
#pragma unroll
        for (int h = 0; h < 128; h++) s += Ls[t * 129 + h];
        g_psum[(n * KK + t) * 8 + blockIdx.x] = s;
    }
}

// ---------------- kernel 4: fold 8 partial sums ----------------
__global__ __launch_bounds__(64) void kAsumF() {
    int n = blockIdx.x, k = threadIdx.x;
    const float* p = g_psum + (size_t)(n * KK + k) * 8;
    float s = 0.f;
#pragma unroll
    for (int i = 0; i < 8; i++) s += p[i];
    g_asum[n * KK + k] = s;
}

// ---------------- kernel 5: vlad GEMM via mma.sync: D[c=128][k=64] = sum_h xn^T * sa ----------------
__global__ __launch_bounds__(256, 2) void kVladMMA(const float* __restrict__ x,
                                                   const float* __restrict__ w) {
    extern __shared__ char sm[];
    uint32_t sb = smem_u32(sm);
    int t = threadIdx.x, wid = t >> 5, l = t & 31;
    int n = blockIdx.y, cb = blockIdx.x * 128;
    float* sas = (float*)(sm + SM_AUX);
    if (t < 64) sas[t] = g_asum[n * KK + t];

    int mh = (wid & 3) * 32, nk = (wid >> 2) * 32;
    int arow = (l & 7) + ((l >> 3) & 1) * 8, acol = (l >> 4) * 8;
    int brow = (l & 7) + ((l >> 4) & 1) * 8, bcol = ((l >> 3) & 1) * 8;
    uint32_t aHiA = sb + SM_AHI + (mh + arow) * PITCHB + acol * 2;
    uint32_t aLoA = sb + SM_ALO + (mh + arow) * PITCHB + acol * 2;
    uint32_t bHiA = sb + SM_BHI + (nk + brow) * PITCHB + bcol * 2;
    uint32_t bLoA = sb + SM_BLO + (nk + brow) * PITCHB + bcol * 2;

    float acc[2][4][4];
#pragma unroll
    for (int i = 0; i < 2; i++)
#pragma unroll
        for (int j = 0; j < 4; j++)
#pragma unroll
            for (int q = 0; q < 4; q++) acc[i][j][q] = 0.f;

    int srow = t >> 1, scs = (t & 1) * 32;
    int sbr = t >> 2, sbs = (t & 3) * 16;
    const float* xb = x + ((size_t)(n * CC + cb)) * HWD;
    const float* ivb = g_inv + n * HWD;
    const __nv_bfloat16* shb = g_saT_hi + ((size_t)n * KK) * HWD;
    const __nv_bfloat16* slb = g_saT_lo + ((size_t)n * KK) * HWD;

    for (int hbk = 0; hbk < HWD; hbk += 64) {
        __syncthreads();
        {   // stage A: xn^T [c=128][h=64] = x * inv -> hi/lo bf16
            const float4* src = (const float4*)(xb + (size_t)srow * HWD + hbk + scs);
            const float4* ivs = (const float4*)(ivb + hbk + scs);
#pragma unroll
            for (int q = 0; q < 4; q++) {
                float4 v0 = src[2 * q], v1 = src[2 * q + 1];
                float4 i0 = ivs[2 * q], i1 = ivs[2 * q + 1];
                v0.x *= i0.x; v0.y *= i0.y; v0.z *= i0.z; v0.w *= i0.w;
                v1.x *= i1.x; v1.y *= i1.y; v1.z *= i1.z; v1.w *= i1.w;
                B8 H, L;
                split8(v0, v1, H, L);
                uint32_t off = srow * PITCHB + scs * 2 + q * 16;
                *(uint4*)(sm + SM_AHI + off) = H.u;
                *(uint4*)(sm + SM_ALO + off) = L.u;
            }
        }
        {   // stage B: saT hi/lo bf16 passthrough
            const uint4* sh = (const uint4*)(shb + (size_t)sbr * HWD + hbk + sbs);
            const uint4* sl = (const uint4*)(slb + (size_t)sbr * HWD + hbk + sbs);
            uint4 h0 = sh[0], h1 = sh[1], l0 = sl[0], l1 = sl[1];
            uint32_t off = sbr * PITCHB + sbs * 2;
            *(uint4*)(sm + SM_BHI + off) = h0;
            *(uint4*)(sm + SM_BHI + off + 16) = h1;
            *(uint4*)(sm + SM_BLO + off) = l0;
            *(uint4*)(sm + SM_BLO + off + 16) = l1;
        }
        __syncthreads();
#pragma unroll
        for (int kb = 0; kb < 4; kb++) {
            uint32_t ah[2][4], al[2][4];
#pragma unroll
            for (int m2 = 0; m2 < 2; m2++) {
                ldm4(ah[m2], aHiA + m2 * 16 * PITCHB + kb * 32);
                ldm4(al[m2], aLoA + m2 * 16 * PITCHB + kb * 32);
            }
#pragma unroll
            for (int np = 0; np < 2; np++) {
                uint32_t bh[4], bl[4];
                ldm4(bh, bHiA + np * 16 * PITCHB + kb * 32);
                ldm4(bl, bLoA + np * 16 * PITCHB + kb * 32);
#pragma unroll
                for (int m2 = 0; m2 < 2; m2++)
#pragma unroll
                    for (int hf = 0; hf < 2; hf++) {
                        float* d = acc[m2][np * 2 + hf];
                        mma16816(d, ah[m2], bh + hf * 2);
                        mma16816(d, ah[m2], bl + hf * 2);
                        mma16816(d, al[m2], bh + hf * 2);
                    }
            }
        }
    }
    __syncthreads();
    float* Ts = (float*)sm;   // [k=64][129] holding D^T
    int rr = l >> 2, c2 = (l & 3) * 2;
#pragma unroll
    for (int m2 = 0; m2 < 2; m2++)
#pragma unroll
        for (int nb = 0; nb < 4; nb++) {
            float* d = acc[m2][nb];
            int c0 = mh + m2 * 16 + rr, k0 = nk + nb * 8 + c2;
            Ts[k0 * 129 + c0] = d[0];
            Ts[(k0 + 1) * 129 + c0] = d[1];
            Ts[k0 * 129 + c0 + 8] = d[2];
            Ts[(k0 + 1) * 129 + c0 + 8] = d[3];
        }
    __syncthreads();
    {   // writeout with -asum*W^T, coalesced along c
        int cc2 = t & 127, kh = t >> 7;
        float* vb = g_vlad + ((size_t)n * KK) * CC + cb;
        const float* wrow = w + (size_t)(cb + cc2) * KK;
#pragma unroll
        for (int r = 0; r < 32; r++) {
            int k = r * 2 + kh;
            vb[(size_t)k * CC + cc2] = Ts[k * 129 + cc2] - sas[k] * wrow[k];
        }
    }
}

// ---------------- kernel 6: intra-normalize vlad rows -> output ----------------
__global__ __launch_bounds__(128) void kVnorm(float* __restrict__ out) {
    __shared__ float red[4];
    __shared__ float sinv;
    int row = blockIdx.x;
    const float* p = g_vlad + (size_t)row * CC;
    int t = threadIdx.x;
    float v[4];
    float s = 0.f;
#pragma unroll
    for (int j = 0; j < 4; j++) { v[j] = p[t + j * 128]; s += v[j] * v[j]; }
#pragma unroll
    for (int o = 16; o > 0; o >>= 1) s += __shfl_xor_sync(0xffffffffu, s, o);
    int wq = t >> 5;
    if ((t & 31) == 0) red[wq] = s;
    __syncthreads();
    if (t == 0) sinv = 1.f / fmaxf(sqrtf(red[0] + red[1] + red[2] + red[3]), EPSV);
    __syncthreads();
    float inv = sinv;
    float* o = out + (size_t)row * CC;
#pragma unroll
    for (int j = 0; j < 4; j++) o[t + j * 128] = v[j] * inv;
}

extern "C" void kernel_launch(void* const* d_in, const int* in_sizes, int n_in,
                              void* d_out, int out_size) {
    const float* x = (const float*)d_in[0];     // [N,C,H,W]
    const float* w = (const float*)d_in[1];     // [C,K]
    const float* b = (const float*)d_in[2];     // [K]
    float* out = (float*)d_out;

    const size_t VLAD_OFF = 0;
    const size_t SA_OFF = (size_t)NN * KK * CC;
    const size_t FEAT_OFF = SA_OFF + (size_t)NN * KK * HWD;

    cudaFuncSetAttribute(kLogitsMMA, cudaFuncAttributeMaxDynamicSharedMemorySize, SMEM_BYTES);
    cudaFuncSetAttribute(kVladMMA, cudaFuncAttributeMaxDynamicSharedMemorySize, SMEM_BYTES);

    kWnorm<<<1, 256>>>(w);
    kNormFeat<<<dim3(HWD / 16, NN), 256>>>(x, out + FEAT_OFF);
    kLogitsMMA<<<dim3(HWD / 128, NN), 256, SMEM_BYTES>>>(out + FEAT_OFF, b, out + SA_OFF);
    kAsumF<<<NN, 64>>>();
    kVladMMA<<<dim3(CC / 128, NN), 256, SMEM_BYTES>>>(x, w);
    kVnorm<<<NN * KK, 128>>>(out + VLAD_OFF);
}

// round 9
// speedup vs baseline: 1.4173x; 1.0570x over previous
#include <cuda_runtime.h>
#include <cuda_bf16.h>
#include <math.h>
#include <stdint.h>

#define NN 64
#define CC 512
#define HWD 1024
#define KK 64
#define ALPHA 50.0f
#define EPSV 1e-12f

// ---- device scratch ----
__device__ __nv_bfloat16 g_WnT_hi[KK * CC], g_WnT_lo[KK * CC];   // [k][c]
__device__ float g_inv[NN * HWD];
__device__ __nv_bfloat16 g_saT_hi[(size_t)NN * KK * HWD];        // [n][k][h]
__device__ __nv_bfloat16 g_saT_lo[(size_t)NN * KK * HWD];
__device__ float g_psum[NN * KK * 8];
__device__ float g_vlad[(size_t)NN * KK * CC];

// ---- smem layout (bytes). Pitch 144B = 72 bf16 per row. ----
#define SM_AHI 0
#define SM_ALO 18432
#define SM_BHI 36864
#define SM_BLO 46080
#define SM_AUX 55296            // bias[64] fp32
#define SM_SINV 55552           // sinv[128] fp32
#define SM_RED 56064            // red[256] fp32
#define SMEM_BYTES 57344
#define PITCHB 144

__device__ __forceinline__ uint32_t smem_u32(const void* p) {
    uint32_t a;
    asm("{ .reg .u64 t; cvta.to.shared.u64 t, %1; cvt.u32.u64 %0, t; }" : "=r"(a) : "l"(p));
    return a;
}
__device__ __forceinline__ void ldm4(uint32_t* r, uint32_t addr) {
    asm volatile("ldmatrix.sync.aligned.m8n8.x4.shared.b16 {%0,%1,%2,%3}, [%4];"
                 : "=r"(r[0]), "=r"(r[1]), "=r"(r[2]), "=r"(r[3]) : "r"(addr));
}
__device__ __forceinline__ void mma16816(float* d, const uint32_t* a, const uint32_t* b) {
    asm volatile(
        "mma.sync.aligned.m16n8k16.row.col.f32.bf16.bf16.f32 "
        "{%0,%1,%2,%3}, {%4,%5,%6,%7}, {%8,%9}, {%0,%1,%2,%3};"
        : "+f"(d[0]), "+f"(d[1]), "+f"(d[2]), "+f"(d[3])
        : "r"(a[0]), "r"(a[1]), "r"(a[2]), "r"(a[3]), "r"(b[0]), "r"(b[1]));
}

union B8 { uint4 u; __nv_bfloat162 b[4]; };

__device__ __forceinline__ void split8(float4 v0, float4 v1, B8& H, B8& L) {
    H.b[0] = __floats2bfloat162_rn(v0.x, v0.y);
    H.b[1] = __floats2bfloat162_rn(v0.z, v0.w);
    H.b[2] = __floats2bfloat162_rn(v1.x, v1.y);
    H.b[3] = __floats2bfloat162_rn(v1.z, v1.w);
    L.b[0] = __floats2bfloat162_rn(v0.x - __low2float(H.b[0]), v0.y - __high2float(H.b[0]));
    L.b[1] = __floats2bfloat162_rn(v0.z - __low2float(H.b[1]), v0.w - __high2float(H.b[1]));
    L.b[2] = __floats2bfloat162_rn(v1.x - __low2float(H.b[2]), v1.y - __high2float(H.b[2]));
    L.b[3] = __floats2bfloat162_rn(v1.z - __low2float(H.b[3]), v1.w - __high2float(H.b[3]));
}

// ---------------- kernel 1: normalize W columns -> bf16 hi/lo W^T ----------------
__global__ __launch_bounds__(256) void kWnorm(const float* __restrict__ w) {
    __shared__ float part[4][64];
    int t = threadIdx.x;
    int k = t & 63, p = t >> 6;
    float s = 0.f;
    for (int c = p; c < CC; c += 4) { float v = w[c * KK + k]; s += v * v; }
    part[p][k] = s;
    __syncthreads();
    if (p == 0) {
        float tot = part[0][k] + part[1][k] + part[2][k] + part[3][k];
        part[0][k] = 1.f / fmaxf(sqrtf(tot), EPSV);
    }
    __syncthreads();
    float inv = part[0][k];
    for (int c = p; c < CC; c += 4) {
        float v = w[c * KK + k] * inv;
        __nv_bfloat16 hh = __float2bfloat16(v);
        __nv_bfloat16 ll = __float2bfloat16(v - __bfloat162float(hh));
        g_WnT_hi[k * CC + c] = hh;
        g_WnT_lo[k * CC + c] = ll;
    }
}

// ---------------- kernel 2: FUSED norm + feature + logits GEMM + softmax ----------------
// CTA: (n, 128-pixel slab). Phase 1: inv norms. Phase 2: per 64-c chunk:
// stage xn bf16 hi/lo (A), Wn (B), MMA, reconstruct fp32 feat from A smem.
__global__ __launch_bounds__(256, 2) void kLogitsFused(const float* __restrict__ x,
                                                       const float* __restrict__ bias,
                                                       float* __restrict__ feat,
                                                       float* __restrict__ sa_raw) {
    extern __shared__ char sm[];
    uint32_t sb = smem_u32(sm);
    int t = threadIdx.x, wid = t >> 5, l = t & 31;
    int n = blockIdx.y, hb = blockIdx.x * 128;
    float* sbias = (float*)(sm + SM_AUX);
    float* sinv = (float*)(sm + SM_SINV);
    float* red = (float*)(sm + SM_RED);
    if (t < 64) sbias[t] = bias[t];

    int h = t & 127, half = t >> 7;

    // ---- phase 1: per-pixel inv L2 norm over C ----
    {
        const float* xp = x + ((size_t)n * CC + half * 256) * HWD + hb + h;
        float s = 0.f;
#pragma unroll 8
        for (int i = 0; i < 256; i++) { float v = xp[(size_t)i * HWD]; s += v * v; }
        red[t] = s;
    }
    __syncthreads();
    if (t < 128) {
        float iv = 1.f / fmaxf(sqrtf(red[t] + red[t + 128]), EPSV);
        sinv[t] = iv;
        g_inv[n * HWD + hb + t] = iv;
    }
    __syncthreads();

    // ---- phase 2: GEMM over 8 chunks of 64 c ----
    int mh = (wid & 3) * 32, nk = (wid >> 2) * 32;
    int arow = (l & 7) + ((l >> 3) & 1) * 8, acol = (l >> 4) * 8;
    int brow = (l & 7) + ((l >> 4) & 1) * 8, bcol = ((l >> 3) & 1) * 8;
    uint32_t aHiA = sb + SM_AHI + (mh + arow) * PITCHB + acol * 2;
    uint32_t aLoA = sb + SM_ALO + (mh + arow) * PITCHB + acol * 2;
    uint32_t bHiA = sb + SM_BHI + (nk + brow) * PITCHB + bcol * 2;
    uint32_t bLoA = sb + SM_BLO + (nk + brow) * PITCHB + bcol * 2;

    float acc[2][4][4];
#pragma unroll
    for (int i = 0; i < 2; i++)
#pragma unroll
        for (int j = 0; j < 4; j++)
#pragma unroll
            for (int q = 0; q < 4; q++) acc[i][j][q] = 0.f;

    const float* xcol = x + (size_t)n * CC * HWD + hb + h;
    int sbr = t >> 2, sbs = (t & 3) * 16;        // B staging
    int fh0 = t >> 2, fcseg = (t & 3) * 4;       // feat writeout
    float* fbase = feat + ((size_t)(n * HWD + hb)) * CC;

    for (int cb = 0; cb < CC; cb += 64) {
        __syncthreads();
        {   // stage A: xn[h][c] hi/lo; thread covers h, c = cb+half*32 .. +32
            float iv = sinv[h];
#pragma unroll
            for (int q = 0; q < 4; q++) {
                int c0 = cb + half * 32 + q * 8;
                float4 v0, v1;
                v0.x = xcol[(size_t)(c0 + 0) * HWD] * iv;
                v0.y = xcol[(size_t)(c0 + 1) * HWD] * iv;
                v0.z = xcol[(size_t)(c0 + 2) * HWD] * iv;
                v0.w = xcol[(size_t)(c0 + 3) * HWD] * iv;
                v1.x = xcol[(size_t)(c0 + 4) * HWD] * iv;
                v1.y = xcol[(size_t)(c0 + 5) * HWD] * iv;
                v1.z = xcol[(size_t)(c0 + 6) * HWD] * iv;
                v1.w = xcol[(size_t)(c0 + 7) * HWD] * iv;
                B8 H, L;
                split8(v0, v1, H, L);
                uint32_t off = h * PITCHB + (half * 32 + q * 8) * 2;
                *(uint4*)(sm + SM_AHI + off) = H.u;
                *(uint4*)(sm + SM_ALO + off) = L.u;
            }
        }
        {   // stage B: WnT hi/lo passthrough
            const uint4* sh = (const uint4*)(g_WnT_hi + sbr * CC + cb + sbs);
            const uint4* sl = (const uint4*)(g_WnT_lo + sbr * CC + cb + sbs);
            uint4 h0 = sh[0], h1 = sh[1], l0 = sl[0], l1 = sl[1];
            uint32_t off = sbr * PITCHB + sbs * 2;
            *(uint4*)(sm + SM_BHI + off) = h0;
            *(uint4*)(sm + SM_BHI + off + 16) = h1;
            *(uint4*)(sm + SM_BLO + off) = l0;
            *(uint4*)(sm + SM_BLO + off + 16) = l1;
        }
        __syncthreads();
#pragma unroll
        for (int kb = 0; kb < 4; kb++) {
            uint32_t ah[2][4], al[2][4];
#pragma unroll
            for (int m2 = 0; m2 < 2; m2++) {
                ldm4(ah[m2], aHiA + m2 * 16 * PITCHB + kb * 32);
                ldm4(al[m2], aLoA + m2 * 16 * PITCHB + kb * 32);
            }
#pragma unroll
            for (int np = 0; np < 2; np++) {
                uint32_t bh[4], bl[4];
                ldm4(bh, bHiA + np * 16 * PITCHB + kb * 32);
                ldm4(bl, bLoA + np * 16 * PITCHB + kb * 32);
#pragma unroll
                for (int m2 = 0; m2 < 2; m2++)
#pragma unroll
                    for (int hf = 0; hf < 2; hf++) {
                        float* d = acc[m2][np * 2 + hf];
                        mma16816(d, ah[m2], bh + hf * 2);
                        mma16816(d, ah[m2], bl + hf * 2);
                        mma16816(d, al[m2], bh + hf * 2);
                    }
            }
        }
        // feat writeout: fp32 = hi + lo from A smem, 64B-contiguous per h-row
#pragma unroll
        for (int pass = 0; pass < 2; pass++) {
            int fh = fh0 + pass * 64;
#pragma unroll
            for (int i = 0; i < 4; i++) {
                int c = fcseg + i * 16;
                uint2 uh = *(uint2*)(sm + SM_AHI + fh * PITCHB + c * 2);
                uint2 ul = *(uint2*)(sm + SM_ALO + fh * PITCHB + c * 2);
                __nv_bfloat162 h0 = *(__nv_bfloat162*)&uh.x, h1 = *(__nv_bfloat162*)&uh.y;
                __nv_bfloat162 l0 = *(__nv_bfloat162*)&ul.x, l1 = *(__nv_bfloat162*)&ul.y;
                float4 o;
                o.x = __low2float(h0) + __low2float(l0);
                o.y = __high2float(h0) + __high2float(l0);
                o.z = __low2float(h1) + __low2float(l1);
                o.w = __high2float(h1) + __high2float(l1);
                *(float4*)(fbase + (size_t)fh * CC + cb + c) = o;
            }
        }
    }
    __syncthreads();
    // ---- epilogue: logits -> Ls[64][129] (overlays A tiles) ----
    float* Ls = (float*)sm;
    int rr = l >> 2, c2 = (l & 3) * 2;
#pragma unroll
    for (int m2 = 0; m2 < 2; m2++)
#pragma unroll
        for (int nb = 0; nb < 4; nb++) {
            float* d = acc[m2][nb];
            int h0 = mh + m2 * 16 + rr, k0 = nk + nb * 8 + c2;
            Ls[k0 * 129 + h0] = d[0];
            Ls[(k0 + 1) * 129 + h0] = d[1];
            Ls[k0 * 129 + h0 + 8] = d[2];
            Ls[(k0 + 1) * 129 + h0 + 8] = d[3];
        }
    __syncthreads();
    {   // raw logits out
        float* sp = sa_raw + ((size_t)n * KK) * HWD + hb;
        int h2 = t & 127, kh = t >> 7;
#pragma unroll
        for (int r = 0; r < 32; r++) {
            int k = r * 2 + kh;
            sp[(size_t)k * HWD + h2] = Ls[k * 129 + h2];
        }
    }
    __syncthreads();
    if (t < 128) {   // softmax over k for h=t
        float m = -1e30f;
#pragma unroll
        for (int k = 0; k < 64; k++)
            m = fmaxf(m, (Ls[k * 129 + t] + sbias[k]) * ALPHA);
        float s = 0.f;
#pragma unroll
        for (int k = 0; k < 64; k++) {
            float e = __expf((Ls[k * 129 + t] + sbias[k]) * ALPHA - m);
            s += e;
            Ls[k * 129 + t] = e;
        }
        float r = 1.f / s;
#pragma unroll
        for (int k = 0; k < 64; k++) Ls[k * 129 + t] *= r;
    }
    __syncthreads();
    {   // soft-assign bf16 hi/lo
        int h2 = t & 127, kh = t >> 7;
        __nv_bfloat16* gh = g_saT_hi + ((size_t)n * KK) * HWD + hb;
        __nv_bfloat16* gl = g_saT_lo + ((size_t)n * KK) * HWD + hb;
#pragma unroll
        for (int r = 0; r < 32; r++) {
            int k = r * 2 + kh;
            float v = Ls[k * 129 + h2];
            __nv_bfloat16 hh = __float2bfloat16(v);
            __nv_bfloat16 ll = __float2bfloat16(v - __bfloat162float(hh));
            gh[(size_t)k * HWD + h2] = hh;
            gl[(size_t)k * HWD + h2] = ll;
        }
    }
    if (t < 64) {   // deterministic partial sums
        float s = 0.f;
#pragma unroll
        for (int hq = 0; hq < 128; hq++) s += Ls[t * 129 + hq];
        g_psum[(n * KK + t) * 8 + blockIdx.x] = s;
    }
}

// ---------------- kernel 3: vlad GEMM via mma.sync (asum folded) ----------------
__global__ __launch_bounds__(256, 2) void kVladMMA(const float* __restrict__ x,
                                                   const float* __restrict__ w) {
    extern __shared__ char sm[];
    uint32_t sb = smem_u32(sm);
    int t = threadIdx.x, wid = t >> 5, l = t & 31;
    int n = blockIdx.y, cb = blockIdx.x * 128;
    float* sas = (float*)(sm + SM_AUX);
    if (t < 64) {
        const float* p = g_psum + (size_t)(n * KK + t) * 8;
        float s = 0.f;
#pragma unroll
        for (int i = 0; i < 8; i++) s += p[i];
        sas[t] = s;
    }

    int mh = (wid & 3) * 32, nk = (wid >> 2) * 32;
    int arow = (l & 7) + ((l >> 3) & 1) * 8, acol = (l >> 4) * 8;
    int brow = (l & 7) + ((l >> 4) & 1) * 8, bcol = ((l >> 3) & 1) * 8;
    uint32_t aHiA = sb + SM_AHI + (mh + arow) * PITCHB + acol * 2;
    uint32_t aLoA = sb + SM_ALO + (mh + arow) * PITCHB + acol * 2;
    uint32_t bHiA = sb + SM_BHI + (nk + brow) * PITCHB + bcol * 2;
    uint32_t bLoA = sb + SM_BLO + (nk + brow) * PITCHB + bcol * 2;

    float acc[2][4][4];
#pragma unroll
    for (int i = 0; i < 2; i++)
#pragma unroll
        for (int j = 0; j < 4; j++)
#pragma unroll
            for (int q = 0; q < 4; q++) acc[i][j][q] = 0.f;

    int srow = t >> 1, scs = (t & 1) * 32;
    int sbr = t >> 2, sbs = (t & 3) * 16;
    const float* xb = x + ((size_t)(n * CC + cb)) * HWD;
    const float* ivb = g_inv + n * HWD;
    const __nv_bfloat16* shb = g_saT_hi + ((size_t)n * KK) * HWD;
    const __nv_bfloat16* slb = g_saT_lo + ((size_t)n * KK) * HWD;

    for (int hbk = 0; hbk < HWD; hbk += 64) {
        __syncthreads();
        {   // stage A: xn^T [c=128][h=64]
            const float4* src = (const float4*)(xb + (size_t)srow * HWD + hbk + scs);
            const float4* ivs = (const float4*)(ivb + hbk + scs);
#pragma unroll
            for (int q = 0; q < 4; q++) {
                float4 v0 = src[2 * q], v1 = src[2 * q + 1];
                float4 i0 = ivs[2 * q], i1 = ivs[2 * q + 1];
                v0.x *= i0.x; v0.y *= i0.y; v0.z *= i0.z; v0.w *= i0.w;
                v1.x *= i1.x; v1.y *= i1.y; v1.z *= i1.z; v1.w *= i1.w;
                B8 H, L;
                split8(v0, v1, H, L);
                uint32_t off = srow * PITCHB + scs * 2 + q * 16;
                *(uint4*)(sm + SM_AHI + off) = H.u;
                *(uint4*)(sm + SM_ALO + off) = L.u;
            }
        }
        {   // stage B: saT hi/lo passthrough
            const uint4* sh = (const uint4*)(shb + (size_t)sbr * HWD + hbk + sbs);
            const uint4* sl = (const uint4*)(slb + (size_t)sbr * HWD + hbk + sbs);
            uint4 h0 = sh[0], h1 = sh[1], l0 = sl[0], l1 = sl[1];
            uint32_t off = sbr * PITCHB + sbs * 2;
            *(uint4*)(sm + SM_BHI + off) = h0;
            *(uint4*)(sm + SM_BHI + off + 16) = h1;
            *(uint4*)(sm + SM_BLO + off) = l0;
            *(uint4*)(sm + SM_BLO + off + 16) = l1;
        }
        __syncthreads();
#pragma unroll
        for (int kb = 0; kb < 4; kb++) {
            uint32_t ah[2][4], al[2][4];
#pragma unroll
            for (int m2 = 0; m2 < 2; m2++) {
                ldm4(ah[m2], aHiA + m2 * 16 * PITCHB + kb * 32);
                ldm4(al[m2], aLoA + m2 * 16 * PITCHB + kb * 32);
            }
#pragma unroll
            for (int np = 0; np < 2; np++) {
                uint32_t bh[4], bl[4];
                ldm4(bh, bHiA + np * 16 * PITCHB + kb * 32);
                ldm4(bl, bLoA + np * 16 * PITCHB + kb * 32);
#pragma unroll
                for (int m2 = 0; m2 < 2; m2++)
#pragma unroll
                    for (int hf = 0; hf < 2; hf++) {
                        float* d = acc[m2][np * 2 + hf];
                        mma16816(d, ah[m2], bh + hf * 2);
                        mma16816(d, ah[m2], bl + hf * 2);
                        mma16816(d, al[m2], bh + hf * 2);
                    }
            }
        }
    }
    __syncthreads();
    float* Ts = (float*)sm;   // [k=64][129] holding D^T
    int rr = l >> 2, c2 = (l & 3) * 2;
#pragma unroll
    for (int m2 = 0; m2 < 2; m2++)
#pragma unroll
        for (int nb = 0; nb < 4; nb++) {
            float* d = acc[m2][nb];
            int c0 = mh + m2 * 16 + rr, k0 = nk + nb * 8 + c2;
            Ts[k0 * 129 + c0] = d[0];
            Ts[(k0 + 1) * 129 + c0] = d[1];
            Ts[k0 * 129 + c0 + 8] = d[2];
            Ts[(k0 + 1) * 129 + c0 + 8] = d[3];
        }
    __syncthreads();
    {   // writeout with -asum*W^T
        int cc2 = t & 127, kh = t >> 7;
        float* vb = g_vlad + ((size_t)n * KK) * CC + cb;
        const float* wrow = w + (size_t)(cb + cc2) * KK;
#pragma unroll
        for (int r = 0; r < 32; r++) {
            int k = r * 2 + kh;
            vb[(size_t)k * CC + cc2] = Ts[k * 129 + cc2] - sas[k] * wrow[k];
        }
    }
}

// ---------------- kernel 4: intra-normalize vlad rows -> output ----------------
__global__ __launch_bounds__(128) void kVnorm(float* __restrict__ out) {
    __shared__ float red[4];
    __shared__ float sinv;
    int row = blockIdx.x;
    const float* p = g_vlad + (size_t)row * CC;
    int t = threadIdx.x;
    float v[4];
    float s = 0.f;
#pragma unroll
    for (int j = 0; j < 4; j++) { v[j] = p[t + j * 128]; s += v[j] * v[j]; }
#pragma unroll
    for (int o = 16; o > 0; o >>= 1) s += __shfl_xor_sync(0xffffffffu, s, o);
    int wq = t >> 5;
    if ((t & 31) == 0) red[wq] = s;
    __syncthreads();
    if (t == 0) sinv = 1.f / fmaxf(sqrtf(red[0] + red[1] + red[2] + red[3]), EPSV);
    __syncthreads();
    float inv = sinv;
    float* o = out + (size_t)row * CC;
#pragma unroll
    for (int j = 0; j < 4; j++) o[t + j * 128] = v[j] * inv;
}

extern "C" void kernel_launch(void* const* d_in, const int* in_sizes, int n_in,
                              void* d_out, int out_size) {
    const float* x = (const float*)d_in[0];     // [N,C,H,W]
    const float* w = (const float*)d_in[1];     // [C,K]
    const float* b = (const float*)d_in[2];     // [K]
    float* out = (float*)d_out;

    const size_t VLAD_OFF = 0;
    const size_t SA_OFF = (size_t)NN * KK * CC;
    const size_t FEAT_OFF = SA_OFF + (size_t)NN * KK * HWD;

    cudaFuncSetAttribute(kLogitsFused, cudaFuncAttributeMaxDynamicSharedMemorySize, SMEM_BYTES);
    cudaFuncSetAttribute(kVladMMA, cudaFuncAttributeMaxDynamicSharedMemorySize, SMEM_BYTES);

    kWnorm<<<1, 256>>>(w);
    kLogitsFused<<<dim3(HWD / 128, NN), 256, SMEM_BYTES>>>(x, b, out + FEAT_OFF, out + SA_OFF);
    kVladMMA<<<dim3(CC / 128, NN), 256, SMEM_BYTES>>>(x, w);
    kVnorm<<<NN * KK, 128>>>(out + VLAD_OFF);
}